// round 1
// baseline (speedup 1.0000x reference)
#include <cuda_runtime.h>
#include <math.h>

#define NCELL 512
#define C 32
#define CAP 1536          // max points per bin (mean 976.6, sigma 31 -> 18 sigma margin)
#define SPLITS 8          // CTAs per bin for scatter/gather

// -------- static scratch (no cudaMalloc allowed) --------
__device__ int   g_count[NCELL];
__device__ int4  g_rec[NCELL * CAP];      // {point idx, fx, fy, fz (bits)}
__device__ float g_img[NCELL * C];        // scattered lattice
__device__ float g_h1 [NCELL * C];        // encoder conv out
__device__ float g_t  [NCELL * C];        // inner conv raw
__device__ float g_h2 [NCELL * C];        // residual + silu
__device__ float g_out[NCELL * C];        // decoder conv out
__device__ float g_B  [NCELL * C];        // 2x2x2 box-sum of g_out

// -------- zero accumulated buffers + counters --------
__global__ void zero_k() {
    int j = blockIdx.x * 256 + threadIdx.x;
    if (j < NCELL) g_count[j] = 0;
    if (j < NCELL * C) {
        g_img[j] = 0.f; g_h1[j] = 0.f; g_t[j] = 0.f; g_out[j] = 0.f;
    }
}

// -------- bin points by base cell, store {idx, frac} records --------
__global__ void bin_k(const float* __restrict__ pos, int N) {
    int p = blockIdx.x * 256 + threadIdx.x;
    if (p >= N) return;
    float sx = pos[3 * p + 0] * 8.f;
    float sy = pos[3 * p + 1] * 8.f;
    float sz = pos[3 * p + 2] * 8.f;
    float bx = floorf(sx), by = floorf(sy), bz = floorf(sz);
    int ix = ((int)bx) & 7, iy = ((int)by) & 7, iz = ((int)bz) & 7;
    int cell = (ix << 6) | (iy << 3) | iz;
    int slot = atomicAdd(&g_count[cell], 1);
    if (slot < CAP) {
        int4 r;
        r.x = p;
        r.y = __float_as_int(sx - bx);
        r.z = __float_as_int(sy - by);
        r.w = __float_as_int(sz - bz);
        g_rec[cell * CAP + slot] = r;
    }
}

// -------- scatter: per-bin register accumulation, pipelined loads --------
__global__ void scatter_k(const float* __restrict__ feat) {
    const int b     = blockIdx.x >> 3;      // bin
    const int slice = blockIdx.x & 7;
    const int w     = threadIdx.x >> 5;
    const int lane  = threadIdx.x & 31;
    const int stride = SPLITS * 8;          // 64 warp-slices per bin

    int cnt = g_count[b]; if (cnt > CAP) cnt = CAP;
    const int4* rec = g_rec + b * CAP;

    float a0=0,a1=0,a2=0,a3=0,a4=0,a5=0,a6=0,a7=0;

    int j = slice * 8 + w;
    int4 r0 = make_int4(0,0,0,0), r1 = make_int4(0,0,0,0);
    float f0 = 0.f;
    if (j < cnt)            r0 = __ldg(rec + j);
    if (j + stride < cnt)   r1 = __ldg(rec + j + stride);
    if (j < cnt)            f0 = __ldg(feat + r0.x * C + lane);

    while (j < cnt) {
        int4 rc = r0; float fc = f0;
        int jn = j + stride;
        r0 = r1;
        if (jn + stride < cnt) r1 = __ldg(rec + jn + stride);
        if (jn < cnt)          f0 = __ldg(feat + r0.x * C + lane);

        float fx = __int_as_float(rc.y);
        float fy = __int_as_float(rc.z);
        float fz = __int_as_float(rc.w);
        float gx = 1.f - fx, gy = 1.f - fy, gz = 1.f - fz;
        float w00 = gy * gz, w01 = gy * fz, w10 = fy * gz, w11 = fy * fz;
        float p0 = gx * fc, p1 = fx * fc;
        a0 += w00 * p0; a1 += w01 * p0; a2 += w10 * p0; a3 += w11 * p0;
        a4 += w00 * p1; a5 += w01 * p1; a6 += w10 * p1; a7 += w11 * p1;
        j = jn;
    }

    __shared__ float s_all[8][8][32];       // [src warp][corner][lane]
    s_all[w][0][lane] = a0; s_all[w][1][lane] = a1;
    s_all[w][2][lane] = a2; s_all[w][3][lane] = a3;
    s_all[w][4][lane] = a4; s_all[w][5][lane] = a5;
    s_all[w][6][lane] = a6; s_all[w][7][lane] = a7;
    __syncthreads();

    // warp w reduces corner w across the 8 source warps, one RED per lane
    float s = 0.f;
    #pragma unroll
    for (int q = 0; q < 8; q++) s += s_all[q][w][lane];
    int bx = b >> 6, by = (b >> 3) & 7, bz = b & 7;
    int cx = (bx + (w >> 2)) & 7;
    int cy = (by + ((w >> 1) & 1)) & 7;
    int cz = (bz + (w & 1)) & 7;
    atomicAdd(&g_img[((cx << 6) | (cy << 3) | cz) * C + lane], s);
}

// -------- periodic 3x3x3 conv: grid = 27 taps x 8 x-slabs --------
// stage: 0 img->h1 (encoder), 1 h1->t (inner), 2 h2->out (decoder)
__global__ void conv_k(const float* __restrict__ kern, int stage) {
    const float* src = (stage == 0) ? g_img : (stage == 1) ? g_h1 : g_h2;
    float*       dst = (stage == 0) ? g_h1  : (stage == 1) ? g_t  : g_out;

    __shared__ float s_in[64 * 32];
    const int tid = threadIdx.x;
    const int o = tid & 31, w = tid >> 5;
    const int tap = blockIdx.x % 27;
    const int grp = blockIdx.x / 27;                  // x slab
    const int dx = tap / 9 - 1, dy = (tap / 3) % 3 - 1, dz = tap % 3 - 1;
    const int sx = (grp + dx) & 7;

    #pragma unroll
    for (int k = 0; k < 8; k++) {
        int lc = w * 8 + k;
        int y = lc >> 3, z = lc & 7;
        int scell = (sx << 6) | (((y + dy) & 7) << 3) | ((z + dz) & 7);
        s_in[lc * 32 + o] = src[scell * 32 + o];
    }

    float4 kv[8];
    const float4* kp = reinterpret_cast<const float4*>(kern + (tap * 32 + o) * 32);
    #pragma unroll
    for (int i = 0; i < 8; i++) kv[i] = kp[i];
    __syncthreads();

    float acc[8] = {0,0,0,0,0,0,0,0};
    #pragma unroll
    for (int i4 = 0; i4 < 8; i4++) {
        #pragma unroll
        for (int k = 0; k < 8; k++) {
            float4 sv = *reinterpret_cast<const float4*>(&s_in[(w * 8 + k) * 32 + i4 * 4]);
            acc[k] += sv.x * kv[i4].x + sv.y * kv[i4].y
                    + sv.z * kv[i4].z + sv.w * kv[i4].w;
        }
    }
    #pragma unroll
    for (int k = 0; k < 8; k++)
        atomicAdd(&dst[(grp * 64 + w * 8 + k) * 32 + o], acc[k]);
}

// -------- residual + silu: h2 = h1 + t * sigmoid(t) --------
__global__ void epi_k() {
    int j = blockIdx.x * 256 + threadIdx.x;
    if (j < NCELL * C) {
        float t = g_t[j];
        g_h2[j] = g_h1[j] + t * (1.f / (1.f + __expf(-t)));
    }
}

// -------- 2x2x2 periodic box-sum of decoder output --------
__global__ void box_k() {
    int j = blockIdx.x * 256 + threadIdx.x;
    if (j >= NCELL * C) return;
    int o = j & 31, cell = j >> 5;
    int x = cell >> 6, y = (cell >> 3) & 7, z = cell & 7;
    float s = 0.f;
    #pragma unroll
    for (int k = 0; k < 8; k++) {
        int cx = (x + (k >> 2)) & 7;
        int cy = (y + ((k >> 1) & 1)) & 7;
        int cz = (z + (k & 1)) & 7;
        s += g_out[(((cx << 6) | (cy << 3) | cz) << 5) + o];
    }
    g_B[j] = s;
}

// -------- gather: out[p,:] = B[base_cell(p),:] --------
__global__ void gather_k(float* __restrict__ out) {
    const int b     = blockIdx.x >> 3;
    const int slice = blockIdx.x & 7;
    const int w     = threadIdx.x >> 5;
    const int lane  = threadIdx.x & 31;
    int cnt = g_count[b]; if (cnt > CAP) cnt = CAP;
    float v = g_B[b * 32 + lane];
    const int4* rec = g_rec + b * CAP;
    #pragma unroll 4
    for (int j = slice * 8 + w; j < cnt; j += SPLITS * 8) {
        int idx = __ldg(&rec[j].x);
        out[idx * 32 + lane] = v;
    }
}

extern "C" void kernel_launch(void* const* d_in, const int* in_sizes, int n_in,
                              void* d_out, int out_size) {
    const float* pos  = (const float*)d_in[0];
    const float* feat = (const float*)d_in[1];
    const float* enc  = (const float*)d_in[2];
    const float* inn  = (const float*)d_in[3];   // (1,3,3,3,32,32) == (3,3,3,32,32)
    const float* dec  = (const float*)d_in[4];
    float* out = (float*)d_out;
    int N = in_sizes[0] / 3;

    zero_k   <<<64, 256>>>();
    bin_k    <<<(N + 255) / 256, 256>>>(pos, N);
    scatter_k<<<NCELL * SPLITS, 256>>>(feat);
    conv_k   <<<216, 256>>>(enc, 0);
    conv_k   <<<216, 256>>>(inn, 1);
    epi_k    <<<64, 256>>>();
    conv_k   <<<216, 256>>>(dec, 2);
    box_k    <<<64, 256>>>();
    gather_k <<<NCELL * SPLITS, 256>>>(out);
}